// round 5
// baseline (speedup 1.0000x reference)
#include <cuda_runtime.h>
#include <cuda_bf16.h>
#include <cstdint>

// Problem constants
#define NN 4
#define CC 64
#define HH 96
#define WW 96
#define PP (HH * WW)       // 9216
#define OO 1728            // 3*C*9
#define KTOT 2304          // 256*9

// Scratch (__device__ globals per alloc-free rule)
__device__ float g_kern[(size_t)NN * OO * PP];      // per-pixel kernels
__device__ float g_cat[(size_t)NN * 4 * CC * PP];   // concat(x, r1, r3, r5)
__device__ unsigned g_yh[(size_t)NN * PP * 32];     // y transposed bf16-hi pairs [n][px][kp]
__device__ unsigned g_yl[(size_t)NN * PP * 32];     // bf16-lo
__device__ unsigned g_w1h[OO * 32];                 // gen_w bf16-hi pairs [o][kp]
__device__ unsigned g_w1l[OO * 32];
__device__ unsigned g_wBh[16 * 9 * 8 * 64];         // fuse_w packed [chunk][tap][kp][co]
__device__ unsigned g_wBl[16 * 9 * 8 * 64];

// ---- bf16 split helpers ----
static __device__ __forceinline__ void bsplit(float v, unsigned short& h, unsigned short& l) {
    __nv_bfloat16 bh = __float2bfloat16_rn(v);
    float r = v - __bfloat162float(bh);
    __nv_bfloat16 bl = __float2bfloat16_rn(r);
    h = __bfloat16_as_ushort(bh);
    l = __bfloat16_as_ushort(bl);
}
static __device__ __forceinline__ unsigned pk(unsigned short lo, unsigned short hi) {
    return ((unsigned)hi << 16) | lo;
}

// ---- warp mma: m16n8k16 bf16 (sm_80+ portable; HMMA on Blackwell) ----
static __device__ __forceinline__ void mma16816(
    float& d0, float& d1, float& d2, float& d3,
    uint32_t a0, uint32_t a1, uint32_t a2, uint32_t a3,
    uint32_t b0, uint32_t b1)
{
    asm volatile(
        "mma.sync.aligned.m16n8k16.row.col.f32.bf16.bf16.f32 "
        "{%0,%1,%2,%3}, {%4,%5,%6,%7}, {%8,%9}, {%0,%1,%2,%3};"
        : "+f"(d0), "+f"(d1), "+f"(d2), "+f"(d3)
        : "r"(a0), "r"(a1), "r"(a2), "r"(a3), "r"(b0), "r"(b1));
}

// ============================================================
// prep_y: y[n][k][p] -> g_yh/g_yl [n][px][32 kp] (transposed, split)
// grid (PP/64, NN), 256 thr. smem transpose for coalescing.
// ============================================================
__global__ void __launch_bounds__(256) prep_y(const float* __restrict__ y)
{
    __shared__ float s[64][65];
    const int n  = blockIdx.y;
    const int p0 = blockIdx.x * 64;
    const int tid = threadIdx.x;
#pragma unroll
    for (int pass = 0; pass < 16; pass++) {
        int fid = tid + pass * 256;       // 0..4095
        int k = fid >> 6, px = fid & 63;
        s[k][px] = __ldg(y + ((size_t)n * 64 + k) * PP + p0 + px);
    }
    __syncthreads();
    const int px = tid >> 2, q = tid & 3;
    unsigned hb[8], lb[8];
#pragma unroll
    for (int j = 0; j < 8; j++) {
        int k = q * 16 + j * 2;
        unsigned short h0, l0, h1, l1;
        bsplit(s[k][px], h0, l0);
        bsplit(s[k + 1][px], h1, l1);
        hb[j] = pk(h0, h1);
        lb[j] = pk(l0, l1);
    }
    size_t base = ((size_t)n * PP + p0 + px) * 32 + q * 8;
    *(uint4*)(g_yh + base)     = make_uint4(hb[0], hb[1], hb[2], hb[3]);
    *(uint4*)(g_yh + base + 4) = make_uint4(hb[4], hb[5], hb[6], hb[7]);
    *(uint4*)(g_yl + base)     = make_uint4(lb[0], lb[1], lb[2], lb[3]);
    *(uint4*)(g_yl + base + 4) = make_uint4(lb[4], lb[5], lb[6], lb[7]);
}

// ============================================================
// prep_w1: gen_w[o][k] -> g_w1h/l [o][32 kp]
// ============================================================
__global__ void prep_w1(const float* __restrict__ gen_w)
{
    int idx = blockIdx.x * 256 + threadIdx.x;
    if (idx < OO * 32) {
        int o = idx >> 5, kp = idx & 31;
        unsigned short h0, l0, h1, l1;
        bsplit(__ldg(gen_w + (size_t)o * 64 + 2 * kp), h0, l0);
        bsplit(__ldg(gen_w + (size_t)o * 64 + 2 * kp + 1), h1, l1);
        g_w1h[idx] = pk(h0, h1);
        g_w1l[idx] = pk(l0, l1);
    }
}

// ============================================================
// prep_w3: fuse_w[co][(ci)*9+tap] -> g_wB[chunk][tap][kp][co]
// packed pair = {W[ci=chunk*16+2kp], W[ci..+1]} for that (tap, co)
// ============================================================
__global__ void prep_w3(const float* __restrict__ fuse_w)
{
    int idx = blockIdx.x * 256 + threadIdx.x;
    if (idx < 16 * 9 * 8 * 64) {
        int co  = idx & 63;
        int kp  = (idx >> 6) & 7;
        int tap = (idx >> 9) % 9;
        int chunk = idx / (64 * 8 * 9);
        int k1 = (chunk * 16 + 2 * kp) * 9 + tap;
        unsigned short h0, l0, h1, l1;
        bsplit(__ldg(fuse_w + (size_t)co * KTOT + k1), h0, l0);
        bsplit(__ldg(fuse_w + (size_t)co * KTOT + k1 + 9), h1, l1);
        g_wBh[idx] = pk(h0, h1);
        g_wBl[idx] = pk(l0, l1);
    }
}

// ============================================================
// Stage 1 (mma): g_kern[n][o][px] = sum_k y[n,k,px]*gen_w[o,k] + gen_b[o]
// CTA 128 thr (4 warps, 2M x 2N), tile 128px x 64o, K=64.
// smem rows padded to 144B (72 bf16) -> conflict-free frag LDS.
// ============================================================
#define S1_AH 0
#define S1_AL 18432
#define S1_BH 36864
#define S1_BL 46080
#define S1_SM 55296

__global__ void __launch_bounds__(128) stage1_mma(const float* __restrict__ gen_b)
{
    extern __shared__ __align__(16) char sm[];
    const int n  = blockIdx.z;
    const int o0 = blockIdx.y * 64;
    const int p0 = blockIdx.x * 128;
    const int tid = threadIdx.x;
    const int warp = tid >> 5, lane = tid & 31;
    const int g = lane >> 2, t = lane & 3;
    const int wm = warp & 1, wn = warp >> 1;

    // Copy A (y_t rows) into padded smem
    {
        const uint4* yh = (const uint4*)(g_yh + ((size_t)n * PP + p0) * 32);
        const uint4* yl = (const uint4*)(g_yl + ((size_t)n * PP + p0) * 32);
#pragma unroll
        for (int pass = 0; pass < 8; pass++) {
            int fid = tid + pass * 128;     // 0..1023
            int r = fid >> 3, q = fid & 7;
            *(uint4*)(sm + S1_AH + r * 144 + q * 16) = yh[r * 8 + q];
            *(uint4*)(sm + S1_AL + r * 144 + q * 16) = yl[r * 8 + q];
        }
        const uint4* wh = (const uint4*)(g_w1h + (size_t)o0 * 32);
        const uint4* wl = (const uint4*)(g_w1l + (size_t)o0 * 32);
#pragma unroll
        for (int pass = 0; pass < 4; pass++) {
            int fid = tid + pass * 128;     // 0..511
            int r = fid >> 3, q = fid & 7;
            *(uint4*)(sm + S1_BH + r * 144 + q * 16) = wh[r * 8 + q];
            *(uint4*)(sm + S1_BL + r * 144 + q * 16) = wl[r * 8 + q];
        }
    }
    __syncthreads();

    float d[4][4][4];
#pragma unroll
    for (int i = 0; i < 4; i++)
#pragma unroll
        for (int j = 0; j < 4; j++)
#pragma unroll
            for (int r = 0; r < 4; r++) d[i][j][r] = 0.f;

#pragma unroll
    for (int s = 0; s < 3; s++) {
        const char* A = sm + ((s < 2) ? S1_AH : S1_AL);
        const char* B = sm + ((s == 1) ? S1_BL : S1_BH);
#pragma unroll
        for (int ks = 0; ks < 4; ks++) {
            const int kb = ks * 32 + t * 4;   // byte offset in row
            uint32_t a[4][4], b[4][2];
#pragma unroll
            for (int mi = 0; mi < 4; mi++) {
                const char* p = A + (wm * 64 + mi * 16 + g) * 144 + kb;
                a[mi][0] = *(const uint32_t*)p;
                a[mi][1] = *(const uint32_t*)(p + 8 * 144);
                a[mi][2] = *(const uint32_t*)(p + 16);
                a[mi][3] = *(const uint32_t*)(p + 8 * 144 + 16);
            }
#pragma unroll
            for (int ni = 0; ni < 4; ni++) {
                const char* p = B + (wn * 32 + ni * 8 + g) * 144 + kb;
                b[ni][0] = *(const uint32_t*)p;
                b[ni][1] = *(const uint32_t*)(p + 16);
            }
#pragma unroll
            for (int mi = 0; mi < 4; mi++)
#pragma unroll
                for (int ni = 0; ni < 4; ni++)
                    mma16816(d[mi][ni][0], d[mi][ni][1], d[mi][ni][2], d[mi][ni][3],
                             a[mi][0], a[mi][1], a[mi][2], a[mi][3],
                             b[ni][0], b[ni][1]);
        }
    }

    // Epilogue: c0=(g,2t) c1=(g,2t+1) c2=(g+8,2t) c3=(g+8,2t+1); rows=px, cols=o
#pragma unroll
    for (int mi = 0; mi < 4; mi++) {
        int px = p0 + wm * 64 + mi * 16 + g;
#pragma unroll
        for (int ni = 0; ni < 4; ni++) {
            int o = o0 + wn * 32 + ni * 8 + 2 * t;
            float b0v = __ldg(gen_b + o);
            float b1v = __ldg(gen_b + o + 1);
            float* r0 = g_kern + ((size_t)n * OO + o) * PP;
            float* r1 = r0 + PP;
            r0[px]     = d[mi][ni][0] + b0v;
            r1[px]     = d[mi][ni][1] + b1v;
            r0[px + 8] = d[mi][ni][2] + b0v;
            r1[px + 8] = d[mi][ni][3] + b1v;
        }
    }
}

// ============================================================
// Stage 2: dynamic depthwise convs (d = 1, 3, 5) + build cat
// ============================================================
__global__ void __launch_bounds__(256) stage2_dynconv(const float* __restrict__ x)
{
    const int n = blockIdx.z;
    const int c = blockIdx.y;
    const int p = blockIdx.x * 256 + threadIdx.x;
    const int h = p / WW;
    const int w = p - h * WW;

    const float* xc = x + ((size_t)n * CC + c) * PP;
    const float* kb = g_kern + ((size_t)n * OO + c * 9) * PP + p;

    float acc0 = 0.f, acc1 = 0.f, acc2 = 0.f;
#pragma unroll
    for (int tap = 0; tap < 9; tap++) {
        const int di = tap / 3 - 1;
        const int dj = tap % 3 - 1;
        {
            int hh = h + di, ww2 = w + dj;
            float xv = ((unsigned)hh < (unsigned)HH && (unsigned)ww2 < (unsigned)WW)
                           ? __ldg(xc + hh * WW + ww2) : 0.f;
            acc0 += xv * __ldg(kb + (size_t)tap * PP);
        }
        {
            int hh = h + di * 3, ww2 = w + dj * 3;
            float xv = ((unsigned)hh < (unsigned)HH && (unsigned)ww2 < (unsigned)WW)
                           ? __ldg(xc + hh * WW + ww2) : 0.f;
            acc1 += xv * __ldg(kb + (size_t)(576 + tap) * PP);
        }
        {
            int hh = h + di * 5, ww2 = w + dj * 5;
            float xv = ((unsigned)hh < (unsigned)HH && (unsigned)ww2 < (unsigned)WW)
                           ? __ldg(xc + hh * WW + ww2) : 0.f;
            acc2 += xv * __ldg(kb + (size_t)(1152 + tap) * PP);
        }
    }

    float* cb = g_cat + (size_t)n * 4 * CC * PP + p;
    cb[(size_t)c * PP]            = __ldg(xc + p);
    cb[(size_t)(CC + c) * PP]     = acc0;
    cb[(size_t)(2 * CC + c) * PP] = acc1;
    cb[(size_t)(3 * CC + c) * PP] = acc2;
}

// ============================================================
// Stage 3 (mma): out[n][co][px] = fuse_b[co] + 3x3 conv over cat (256 ci)
// CTA = one row h x 64 co, 256 thr (8 warps: 2M x 4N).
// K = 16 chunks of 16 ci; each tap is one k16 mma with shifted A base.
// A smem [3 dy][100 px'][24 ci-pad] bf16; B smem [9 tap][8 kp][72 co-pad] u32.
// ============================================================
#define S3_AH 0
#define S3_AL 14400
#define S3_BH 28800
#define S3_BL 49536
#define S3_SM 70272

__global__ void __launch_bounds__(256) stage3_mma(
    const float* __restrict__ fuse_b, float* __restrict__ out)
{
    extern __shared__ __align__(16) char sm[];
    const int h = blockIdx.x;
    const int n = blockIdx.y;
    const int tid = threadIdx.x;
    const int warp = tid >> 5, lane = tid & 31;
    const int g = lane >> 2, t = lane & 3;
    const int wm = warp & 1, wn = warp >> 1;   // wm: 48px half, wn: 16co quarter
    const float* catn = g_cat + (size_t)n * 4 * CC * PP;

    float d[3][2][4];
#pragma unroll
    for (int i = 0; i < 3; i++)
#pragma unroll
        for (int j = 0; j < 2; j++)
#pragma unroll
            for (int r = 0; r < 4; r++) d[i][j][r] = 0.f;

#pragma unroll 1
    for (int chunk = 0; chunk < 16; chunk++) {
        const int ci0 = chunk * 16;
        __syncthreads();
        // A: 3 dy x 98 px' x 16 ci, converted to bf16 hi/lo
#pragma unroll
        for (int pass = 0; pass < 21; pass++) {
            int fid = tid + pass * 256;        // 0..5375 = 48*112
            int rrow = fid / 112, u = fid - rrow * 112;
            if (u < 98) {
                int dy = rrow >> 4, ci = rrow & 15;
                int hh = h + dy - 1;
                int w  = u - 1;
                float v = 0.f;
                if ((unsigned)hh < (unsigned)HH && (unsigned)w < (unsigned)WW)
                    v = __ldg(catn + (size_t)(ci0 + ci) * PP + hh * WW + w);
                unsigned short hv, lv;
                bsplit(v, hv, lv);
                int off = (dy * 100 + u) * 24 + ci;   // ushort index
                ((unsigned short*)(sm + S3_AH))[off] = hv;
                ((unsigned short*)(sm + S3_AL))[off] = lv;
            }
        }
        // B: copy packed weights with co padded 64 -> 72
#pragma unroll
        for (int pass = 0; pass < 18; pass++) {
            int fid = tid + pass * 256;        // 0..4607
            int tap = fid >> 9;
            int rem = fid & 511;
            int kp = rem >> 6, co = rem & 63;
            size_t gsrc = (((size_t)chunk * 9 + tap) * 8 + kp) * 64 + co;
            int doff = ((tap * 8 + kp) * 72 + co) * 4;
            *(uint32_t*)(sm + S3_BH + doff) = g_wBh[gsrc];
            *(uint32_t*)(sm + S3_BL + doff) = g_wBl[gsrc];
        }
        __syncthreads();

#pragma unroll
        for (int s = 0; s < 3; s++) {
            const char* A = sm + ((s < 2) ? S3_AH : S3_AL);
            const char* B = sm + ((s == 1) ? S3_BL : S3_BH);
#pragma unroll
            for (int tap = 0; tap < 9; tap++) {
                const int dy = tap / 3, dx = tap % 3;
                uint32_t a[3][4], b[2][2];
#pragma unroll
                for (int mi = 0; mi < 3; mi++) {
                    int pxr = wm * 48 + mi * 16 + g + dx;   // px' index
                    const char* p = A + (dy * 100 + pxr) * 48 + t * 4;
                    a[mi][0] = *(const uint32_t*)p;
                    a[mi][1] = *(const uint32_t*)(p + 8 * 48);
                    a[mi][2] = *(const uint32_t*)(p + 16);
                    a[mi][3] = *(const uint32_t*)(p + 8 * 48 + 16);
                }
#pragma unroll
                for (int ni = 0; ni < 2; ni++) {
                    int co = wn * 16 + ni * 8 + g;
                    const char* p = B + ((tap * 8 + t) * 72 + co) * 4;
                    b[ni][0] = *(const uint32_t*)p;
                    b[ni][1] = *(const uint32_t*)(p + 4 * 72 * 4);
                }
#pragma unroll
                for (int mi = 0; mi < 3; mi++)
#pragma unroll
                    for (int ni = 0; ni < 2; ni++)
                        mma16816(d[mi][ni][0], d[mi][ni][1], d[mi][ni][2], d[mi][ni][3],
                                 a[mi][0], a[mi][1], a[mi][2], a[mi][3],
                                 b[ni][0], b[ni][1]);
            }
        }
    }

    // Epilogue
#pragma unroll
    for (int mi = 0; mi < 3; mi++) {
        int px = h * WW + wm * 48 + mi * 16 + g;
#pragma unroll
        for (int ni = 0; ni < 2; ni++) {
            int co = wn * 16 + ni * 8 + 2 * t;
            float b0v = __ldg(fuse_b + co);
            float b1v = __ldg(fuse_b + co + 1);
            float* r0 = out + ((size_t)n * CC + co) * PP;
            float* r1 = r0 + PP;
            r0[px]     = d[mi][ni][0] + b0v;
            r1[px]     = d[mi][ni][1] + b1v;
            r0[px + 8] = d[mi][ni][2] + b0v;
            r1[px + 8] = d[mi][ni][3] + b1v;
        }
    }
}

// ============================================================
extern "C" void kernel_launch(void* const* d_in, const int* in_sizes, int n_in,
                              void* d_out, int out_size)
{
    (void)in_sizes; (void)n_in; (void)out_size;
    const float* x      = (const float*)d_in[0];
    const float* y      = (const float*)d_in[1];
    const float* gen_w  = (const float*)d_in[2];
    const float* gen_b  = (const float*)d_in[3];
    const float* fuse_w = (const float*)d_in[4];
    const float* fuse_b = (const float*)d_in[5];
    float* out = (float*)d_out;

    cudaFuncSetAttribute(stage1_mma, cudaFuncAttributeMaxDynamicSharedMemorySize, S1_SM);
    cudaFuncSetAttribute(stage3_mma, cudaFuncAttributeMaxDynamicSharedMemorySize, S3_SM);

    prep_y<<<dim3(PP / 64, NN), 256>>>(y);
    prep_w1<<<(OO * 32 + 255) / 256, 256>>>(gen_w);
    prep_w3<<<(16 * 9 * 8 * 64 + 255) / 256, 256>>>(fuse_w);

    stage1_mma<<<dim3(PP / 128, OO / 64, NN), 128, S1_SM>>>(gen_b);

    stage2_dynconv<<<dim3(PP / 256, CC, NN), 256>>>(x);

    stage3_mma<<<dim3(HH, NN), 256, S3_SM>>>(fuse_b, out);
}

// round 6
// speedup vs baseline: 1.1812x; 1.1812x over previous
#include <cuda_runtime.h>
#include <cuda_bf16.h>
#include <cstdint>

// Problem constants
#define NN 4
#define CC 64
#define HH 96
#define WW 96
#define PP (HH * WW)       // 9216
#define OO 1728            // 3*C*9
#define KTOT 2304          // 256*9

// Scratch (__device__ globals per alloc-free rule)
__device__ float g_kern[(size_t)NN * OO * PP];      // per-pixel kernels (f32)
__device__ unsigned g_ch[(size_t)NN * 128 * PP];    // cat bf16-hi pairs [n][ci_pair][px]
__device__ unsigned g_cl[(size_t)NN * 128 * PP];    // cat bf16-lo pairs
__device__ unsigned g_yh[(size_t)NN * PP * 32];     // y transposed bf16-hi pairs [n][px][kp]
__device__ unsigned g_yl[(size_t)NN * PP * 32];
__device__ unsigned g_w1h[OO * 32];                 // gen_w bf16 pairs [o][kp]
__device__ unsigned g_w1l[OO * 32];
__device__ unsigned g_wBh[16 * 9 * 8 * 64];         // fuse_w packed [chunk][tap][kp][co]
__device__ unsigned g_wBl[16 * 9 * 8 * 64];

// ---- bf16 split helpers ----
static __device__ __forceinline__ void bsplit(float v, unsigned short& h, unsigned short& l) {
    __nv_bfloat16 bh = __float2bfloat16_rn(v);
    float r = v - __bfloat162float(bh);
    __nv_bfloat16 bl = __float2bfloat16_rn(r);
    h = __bfloat16_as_ushort(bh);
    l = __bfloat16_as_ushort(bl);
}
static __device__ __forceinline__ unsigned pk(unsigned short lo, unsigned short hi) {
    return ((unsigned)hi << 16) | lo;
}
static __device__ __forceinline__ uint32_t smem_u32(const void* p) {
    uint32_t a;
    asm("{ .reg .u64 t; cvta.to.shared.u64 t, %1; cvt.u32.u64 %0, t; }" : "=r"(a) : "l"(p));
    return a;
}

// ---- warp mma m16n8k16 bf16 + ldmatrix (sm_80/75+ portable) ----
static __device__ __forceinline__ void mma16816(
    float& d0, float& d1, float& d2, float& d3,
    uint32_t a0, uint32_t a1, uint32_t a2, uint32_t a3,
    uint32_t b0, uint32_t b1)
{
    asm volatile(
        "mma.sync.aligned.m16n8k16.row.col.f32.bf16.bf16.f32 "
        "{%0,%1,%2,%3}, {%4,%5,%6,%7}, {%8,%9}, {%0,%1,%2,%3};"
        : "+f"(d0), "+f"(d1), "+f"(d2), "+f"(d3)
        : "r"(a0), "r"(a1), "r"(a2), "r"(a3), "r"(b0), "r"(b1));
}
static __device__ __forceinline__ void ldsm_x4(
    uint32_t& a0, uint32_t& a1, uint32_t& a2, uint32_t& a3, uint32_t addr)
{
    asm volatile(
        "ldmatrix.sync.aligned.m8n8.x4.shared.b16 {%0,%1,%2,%3}, [%4];"
        : "=r"(a0), "=r"(a1), "=r"(a2), "=r"(a3) : "r"(addr));
}

// ============================================================
// prep_y: y[n][k][p] -> g_yh/g_yl [n][px][32 kp]
// ============================================================
__global__ void __launch_bounds__(256) prep_y(const float* __restrict__ y)
{
    __shared__ float s[64][65];
    const int n  = blockIdx.y;
    const int p0 = blockIdx.x * 64;
    const int tid = threadIdx.x;
#pragma unroll
    for (int pass = 0; pass < 16; pass++) {
        int fid = tid + pass * 256;
        int k = fid >> 6, px = fid & 63;
        s[k][px] = __ldg(y + ((size_t)n * 64 + k) * PP + p0 + px);
    }
    __syncthreads();
    const int px = tid >> 2, q = tid & 3;
    unsigned hb[8], lb[8];
#pragma unroll
    for (int j = 0; j < 8; j++) {
        int k = q * 16 + j * 2;
        unsigned short h0, l0, h1, l1;
        bsplit(s[k][px], h0, l0);
        bsplit(s[k + 1][px], h1, l1);
        hb[j] = pk(h0, h1);
        lb[j] = pk(l0, l1);
    }
    size_t base = ((size_t)n * PP + p0 + px) * 32 + q * 8;
    *(uint4*)(g_yh + base)     = make_uint4(hb[0], hb[1], hb[2], hb[3]);
    *(uint4*)(g_yh + base + 4) = make_uint4(hb[4], hb[5], hb[6], hb[7]);
    *(uint4*)(g_yl + base)     = make_uint4(lb[0], lb[1], lb[2], lb[3]);
    *(uint4*)(g_yl + base + 4) = make_uint4(lb[4], lb[5], lb[6], lb[7]);
}

// ============================================================
// prep_w1: gen_w[o][k] -> g_w1h/l [o][32 kp]
// ============================================================
__global__ void prep_w1(const float* __restrict__ gen_w)
{
    int idx = blockIdx.x * 256 + threadIdx.x;
    if (idx < OO * 32) {
        int o = idx >> 5, kp = idx & 31;
        unsigned short h0, l0, h1, l1;
        bsplit(__ldg(gen_w + (size_t)o * 64 + 2 * kp), h0, l0);
        bsplit(__ldg(gen_w + (size_t)o * 64 + 2 * kp + 1), h1, l1);
        g_w1h[idx] = pk(h0, h1);
        g_w1l[idx] = pk(l0, l1);
    }
}

// ============================================================
// prep_w3: fuse_w[co][ci*9+tap] -> g_wB[chunk][tap][kp][co]
// ============================================================
__global__ void prep_w3(const float* __restrict__ fuse_w)
{
    int idx = blockIdx.x * 256 + threadIdx.x;
    if (idx < 16 * 9 * 8 * 64) {
        int co  = idx & 63;
        int kp  = (idx >> 6) & 7;
        int tap = (idx >> 9) % 9;
        int chunk = idx / (64 * 8 * 9);
        int k1 = (chunk * 16 + 2 * kp) * 9 + tap;
        unsigned short h0, l0, h1, l1;
        bsplit(__ldg(fuse_w + (size_t)co * KTOT + k1), h0, l0);
        bsplit(__ldg(fuse_w + (size_t)co * KTOT + k1 + 9), h1, l1);
        g_wBh[idx] = pk(h0, h1);
        g_wBl[idx] = pk(l0, l1);
    }
}

// ============================================================
// Stage 1 (mma, unchanged from R5): g_kern = y^T @ gen_w^T + b
// ============================================================
#define S1_AH 0
#define S1_AL 18432
#define S1_BH 36864
#define S1_BL 46080
#define S1_SM 55296

__global__ void __launch_bounds__(128) stage1_mma(const float* __restrict__ gen_b)
{
    extern __shared__ __align__(16) char sm[];
    const int n  = blockIdx.z;
    const int o0 = blockIdx.y * 64;
    const int p0 = blockIdx.x * 128;
    const int tid = threadIdx.x;
    const int warp = tid >> 5, lane = tid & 31;
    const int g = lane >> 2, t = lane & 3;
    const int wm = warp & 1, wn = warp >> 1;

    {
        const uint4* yh = (const uint4*)(g_yh + ((size_t)n * PP + p0) * 32);
        const uint4* yl = (const uint4*)(g_yl + ((size_t)n * PP + p0) * 32);
#pragma unroll
        for (int pass = 0; pass < 8; pass++) {
            int fid = tid + pass * 128;
            int r = fid >> 3, q = fid & 7;
            *(uint4*)(sm + S1_AH + r * 144 + q * 16) = yh[r * 8 + q];
            *(uint4*)(sm + S1_AL + r * 144 + q * 16) = yl[r * 8 + q];
        }
        const uint4* wh = (const uint4*)(g_w1h + (size_t)o0 * 32);
        const uint4* wl = (const uint4*)(g_w1l + (size_t)o0 * 32);
#pragma unroll
        for (int pass = 0; pass < 4; pass++) {
            int fid = tid + pass * 128;
            int r = fid >> 3, q = fid & 7;
            *(uint4*)(sm + S1_BH + r * 144 + q * 16) = wh[r * 8 + q];
            *(uint4*)(sm + S1_BL + r * 144 + q * 16) = wl[r * 8 + q];
        }
    }
    __syncthreads();

    float d[4][4][4];
#pragma unroll
    for (int i = 0; i < 4; i++)
#pragma unroll
        for (int j = 0; j < 4; j++)
#pragma unroll
            for (int r = 0; r < 4; r++) d[i][j][r] = 0.f;

#pragma unroll
    for (int s = 0; s < 3; s++) {
        const char* A = sm + ((s < 2) ? S1_AH : S1_AL);
        const char* B = sm + ((s == 1) ? S1_BL : S1_BH);
#pragma unroll
        for (int ks = 0; ks < 4; ks++) {
            const int kb = ks * 32 + t * 4;
            uint32_t a[4][4], b[4][2];
#pragma unroll
            for (int mi = 0; mi < 4; mi++) {
                const char* p = A + (wm * 64 + mi * 16 + g) * 144 + kb;
                a[mi][0] = *(const uint32_t*)p;
                a[mi][1] = *(const uint32_t*)(p + 8 * 144);
                a[mi][2] = *(const uint32_t*)(p + 16);
                a[mi][3] = *(const uint32_t*)(p + 8 * 144 + 16);
            }
#pragma unroll
            for (int ni = 0; ni < 4; ni++) {
                const char* p = B + (wn * 32 + ni * 8 + g) * 144 + kb;
                b[ni][0] = *(const uint32_t*)p;
                b[ni][1] = *(const uint32_t*)(p + 16);
            }
#pragma unroll
            for (int mi = 0; mi < 4; mi++)
#pragma unroll
                for (int ni = 0; ni < 4; ni++)
                    mma16816(d[mi][ni][0], d[mi][ni][1], d[mi][ni][2], d[mi][ni][3],
                             a[mi][0], a[mi][1], a[mi][2], a[mi][3],
                             b[ni][0], b[ni][1]);
        }
    }

#pragma unroll
    for (int mi = 0; mi < 4; mi++) {
        int px = p0 + wm * 64 + mi * 16 + g;
#pragma unroll
        for (int ni = 0; ni < 4; ni++) {
            int o = o0 + wn * 32 + ni * 8 + 2 * t;
            float b0v = __ldg(gen_b + o);
            float b1v = __ldg(gen_b + o + 1);
            float* r0 = g_kern + ((size_t)n * OO + o) * PP;
            float* r1 = r0 + PP;
            r0[px]     = d[mi][ni][0] + b0v;
            r1[px]     = d[mi][ni][1] + b1v;
            r0[px + 8] = d[mi][ni][2] + b0v;
            r1[px + 8] = d[mi][ni][3] + b1v;
        }
    }
}

// ============================================================
// Stage 2: dynamic convs for a channel PAIR + emit bf16-split cat pairs
// grid (PP/256, 32, NN)
// ============================================================
__global__ void __launch_bounds__(256) stage2_dynconv(const float* __restrict__ x)
{
    const int n = blockIdx.z;
    const int cp = blockIdx.y;           // channel pair 0..31
    const int c0 = cp * 2;
    const int p = blockIdx.x * 256 + threadIdx.x;
    const int h = p / WW;
    const int w = p - h * WW;

    const float* xc0 = x + ((size_t)n * CC + c0) * PP;
    const float* xc1 = xc0 + PP;
    const float* kb0 = g_kern + ((size_t)n * OO + c0 * 9) * PP + p;
    const float* kb1 = kb0 + (size_t)9 * PP;

    float a0 = 0.f, a1 = 0.f, a2 = 0.f;   // channel c0: d=1,3,5
    float b0 = 0.f, b1 = 0.f, b2 = 0.f;   // channel c0+1
#pragma unroll
    for (int tap = 0; tap < 9; tap++) {
        const int di = tap / 3 - 1;
        const int dj = tap % 3 - 1;
        {
            int hh = h + di, ww2 = w + dj;
            bool ok = ((unsigned)hh < (unsigned)HH && (unsigned)ww2 < (unsigned)WW);
            float x0 = ok ? __ldg(xc0 + hh * WW + ww2) : 0.f;
            float x1 = ok ? __ldg(xc1 + hh * WW + ww2) : 0.f;
            a0 += x0 * __ldg(kb0 + (size_t)tap * PP);
            b0 += x1 * __ldg(kb1 + (size_t)tap * PP);
        }
        {
            int hh = h + di * 3, ww2 = w + dj * 3;
            bool ok = ((unsigned)hh < (unsigned)HH && (unsigned)ww2 < (unsigned)WW);
            float x0 = ok ? __ldg(xc0 + hh * WW + ww2) : 0.f;
            float x1 = ok ? __ldg(xc1 + hh * WW + ww2) : 0.f;
            a1 += x0 * __ldg(kb0 + (size_t)(576 + tap) * PP);
            b1 += x1 * __ldg(kb1 + (size_t)(576 + tap) * PP);
        }
        {
            int hh = h + di * 5, ww2 = w + dj * 5;
            bool ok = ((unsigned)hh < (unsigned)HH && (unsigned)ww2 < (unsigned)WW);
            float x0 = ok ? __ldg(xc0 + hh * WW + ww2) : 0.f;
            float x1 = ok ? __ldg(xc1 + hh * WW + ww2) : 0.f;
            a2 += x0 * __ldg(kb0 + (size_t)(1152 + tap) * PP);
            b2 += x1 * __ldg(kb1 + (size_t)(1152 + tap) * PP);
        }
    }

    // Emit 4 cat sections as bf16 hi/lo pairs: pair idx = sec*32 + cp
    float ev[4], ov[4];
    ev[0] = __ldg(xc0 + p); ov[0] = __ldg(xc1 + p);
    ev[1] = a0; ov[1] = b0;
    ev[2] = a1; ov[2] = b1;
    ev[3] = a2; ov[3] = b2;
#pragma unroll
    for (int sec = 0; sec < 4; sec++) {
        unsigned short he, le, ho, lo;
        bsplit(ev[sec], he, le);
        bsplit(ov[sec], ho, lo);
        size_t gi = ((size_t)n * 128 + sec * 32 + cp) * PP + p;
        g_ch[gi] = pk(he, ho);
        g_cl[gi] = pk(le, lo);
    }
}

// ============================================================
// Stage 3 (mma + ldmatrix): out = fuse_b + 3x3 conv over cat (256 ci)
// CTA = 2 rows (h0, h0+1) x 32 co. grid (48, 2, 4). 256 thr:
// warps = 4 m (192px -> 3 frags each) x 2 n (16 co -> 2 frags each).
// A smem [4 dy][100 px][12 pad] u32-pairs; B smem [9 tap][8 kp][40 pad].
// ============================================================
#define S3A_H 0
#define S3A_L 19200
#define S3B_H 38400
#define S3B_L 49920
#define S3_SM 61440

__global__ void __launch_bounds__(256) stage3_mma(
    const float* __restrict__ fuse_b, float* __restrict__ out)
{
    extern __shared__ __align__(16) char sm[];
    const uint32_t sbase = smem_u32(sm);
    const int h0  = blockIdx.x * 2;
    const int coh = blockIdx.y;          // co half (32 each)
    const int n   = blockIdx.z;
    const int tid = threadIdx.x;
    const int warp = tid >> 5, lane = tid & 31;
    const int g = lane >> 2, t = lane & 3;
    const int wm = warp & 3, wn = warp >> 2;
    const int rsel = lane & 15;
    const int half16 = (lane >> 4) * 16;          // byte offset for k-half
    const int r    = wm >> 1;                     // output row within pair
    const int pxcb = (wm & 1) * 48;               // px base for this warp

    float d[3][2][4];
#pragma unroll
    for (int i = 0; i < 3; i++)
#pragma unroll
        for (int j = 0; j < 2; j++)
#pragma unroll
            for (int q = 0; q < 4; q++) d[i][j][q] = 0.f;

#pragma unroll 1
    for (int chunk = 0; chunk < 16; chunk++) {
        __syncthreads();
        // A loader: 4 dy-rows x 8 pairs x 112(pad) entries
#pragma unroll
        for (int pass = 0; pass < 14; pass++) {
            int fid = tid + pass * 256;           // 0..3583
            int row = fid >> 7;                   // /112? use 128 pad -> need 4*8*112=3584; fid/112:
            // exact: row = fid / 112
            row = fid / 112;
            int u = fid - row * 112;
            int dyrow = row >> 3, kpl = row & 7;
            if (u < 98) {
                int hh = h0 + dyrow - 1;
                int w  = u - 1;
                uint32_t vh = 0, vl = 0;
                if ((unsigned)hh < (unsigned)HH && (unsigned)w < (unsigned)WW) {
                    size_t gi = ((size_t)n * 128 + chunk * 8 + kpl) * PP + hh * WW + w;
                    vh = g_ch[gi];
                    vl = g_cl[gi];
                }
                int so = ((dyrow * 100 + u) * 12 + kpl) * 4;
                *(uint32_t*)(sm + S3A_H + so) = vh;
                *(uint32_t*)(sm + S3A_L + so) = vl;
            }
        }
        // B loader: 72 x 32
#pragma unroll
        for (int pass = 0; pass < 9; pass++) {
            int fid = tid + pass * 256;           // 0..2303
            int tapk = fid >> 5;                  // tap*8+kp
            int coL  = fid & 31;
            size_t gi = ((size_t)chunk * 72 + tapk) * 64 + coh * 32 + coL;
            int so = (tapk * 40 + coL) * 4;
            *(uint32_t*)(sm + S3B_H + so) = g_wBh[gi];
            *(uint32_t*)(sm + S3B_L + so) = g_wBl[gi];
        }
        __syncthreads();

#pragma unroll
        for (int s = 0; s < 3; s++) {
            const uint32_t Ab = sbase + ((s < 2) ? S3A_H : S3A_L) + rsel * 48 + half16;
            const char*    Bp = sm + ((s == 1) ? S3B_L : S3B_H);
#pragma unroll
            for (int tap = 0; tap < 9; tap++) {
                const int dy = tap / 3, dx = tap % 3;
                uint32_t b[2][2];
#pragma unroll
                for (int ni = 0; ni < 2; ni++) {
                    int coL = wn * 16 + ni * 8 + g;
                    b[ni][0] = *(const uint32_t*)(Bp + ((tap * 8 + t) * 40 + coL) * 4);
                    b[ni][1] = *(const uint32_t*)(Bp + ((tap * 8 + t + 4) * 40 + coL) * 4);
                }
#pragma unroll
                for (int mi = 0; mi < 3; mi++) {
                    int dyrow = r + dy;
                    int px0   = pxcb + mi * 16 + dx;
                    uint32_t a0, a1, a2, a3;
                    ldsm_x4(a0, a1, a2, a3, Ab + (dyrow * 100 + px0) * 48);
#pragma unroll
                    for (int ni = 0; ni < 2; ni++)
                        mma16816(d[mi][ni][0], d[mi][ni][1], d[mi][ni][2], d[mi][ni][3],
                                 a0, a1, a2, a3, b[ni][0], b[ni][1]);
                }
            }
        }
    }

    // Epilogue
#pragma unroll
    for (int mi = 0; mi < 3; mi++) {
        int pxrow = h0 + r;
        int pxcol = pxcb + mi * 16 + g;
#pragma unroll
        for (int ni = 0; ni < 2; ni++) {
            int co = coh * 32 + wn * 16 + ni * 8 + 2 * t;
            float b0v = __ldg(fuse_b + co);
            float b1v = __ldg(fuse_b + co + 1);
            float* r0 = out + ((size_t)n * CC + co) * PP + pxrow * WW;
            float* r1 = r0 + PP;
            r0[pxcol]     = d[mi][ni][0] + b0v;
            r1[pxcol]     = d[mi][ni][1] + b1v;
            r0[pxcol + 8] = d[mi][ni][2] + b0v;
            r1[pxcol + 8] = d[mi][ni][3] + b1v;
        }
    }
}

// ============================================================
extern "C" void kernel_launch(void* const* d_in, const int* in_sizes, int n_in,
                              void* d_out, int out_size)
{
    (void)in_sizes; (void)n_in; (void)out_size;
    const float* x      = (const float*)d_in[0];
    const float* y      = (const float*)d_in[1];
    const float* gen_w  = (const float*)d_in[2];
    const float* gen_b  = (const float*)d_in[3];
    const float* fuse_w = (const float*)d_in[4];
    const float* fuse_b = (const float*)d_in[5];
    float* out = (float*)d_out;

    cudaFuncSetAttribute(stage1_mma, cudaFuncAttributeMaxDynamicSharedMemorySize, S1_SM);
    cudaFuncSetAttribute(stage3_mma, cudaFuncAttributeMaxDynamicSharedMemorySize, S3_SM);

    prep_y<<<dim3(PP / 64, NN), 256>>>(y);
    prep_w1<<<(OO * 32 + 255) / 256, 256>>>(gen_w);
    prep_w3<<<(16 * 9 * 8 * 64 + 255) / 256, 256>>>(fuse_w);

    stage1_mma<<<dim3(PP / 128, OO / 64, NN), 128, S1_SM>>>(gen_b);

    stage2_dynconv<<<dim3(PP / 256, CC / 2, NN), 256>>>(x);

    stage3_mma<<<dim3(HH / 2, 2, NN), 256, S3_SM>>>(fuse_b, out);
}

// round 7
// speedup vs baseline: 1.9648x; 1.6635x over previous
#include <cuda_runtime.h>
#include <cuda_bf16.h>
#include <cstdint>

// Problem constants
#define NN 4
#define CC 64
#define HH 96
#define WW 96
#define PP (HH * WW)       // 9216
#define OO 1728            // 3*C*9
#define KTOT 2304          // 256*9

// Scratch (__device__ globals per alloc-free rule)
__device__ float g_kern[(size_t)NN * OO * PP];      // per-pixel kernels (f32)
__device__ unsigned g_ch[(size_t)NN * 128 * PP];    // cat bf16-hi pairs [n][ci_pair][px]
__device__ unsigned g_cl[(size_t)NN * 128 * PP];    // cat bf16-lo pairs
__device__ unsigned g_yh[(size_t)NN * PP * 32];     // y transposed bf16-hi pairs [n][px][kp]
__device__ unsigned g_yl[(size_t)NN * PP * 32];
__device__ unsigned g_w1h[OO * 32];                 // gen_w bf16 pairs [o][kp]
__device__ unsigned g_w1l[OO * 32];
__device__ unsigned g_wBh[16 * 9 * 8 * 64];         // fuse_w packed [chunk][tap][kp][co]
__device__ unsigned g_wBl[16 * 9 * 8 * 64];

// ---- bf16 split helpers ----
static __device__ __forceinline__ void bsplit(float v, unsigned short& h, unsigned short& l) {
    __nv_bfloat16 bh = __float2bfloat16_rn(v);
    float r = v - __bfloat162float(bh);
    __nv_bfloat16 bl = __float2bfloat16_rn(r);
    h = __bfloat16_as_ushort(bh);
    l = __bfloat16_as_ushort(bl);
}
static __device__ __forceinline__ unsigned pk(unsigned short lo, unsigned short hi) {
    return ((unsigned)hi << 16) | lo;
}
static __device__ __forceinline__ uint32_t smem_u32(const void* p) {
    uint32_t a;
    asm("{ .reg .u64 t; cvta.to.shared.u64 t, %1; cvt.u32.u64 %0, t; }" : "=r"(a) : "l"(p));
    return a;
}

// ---- warp mma m16n8k16 bf16 + ldmatrix + cp.async (sm_80 portable) ----
static __device__ __forceinline__ void mma16816(
    float& d0, float& d1, float& d2, float& d3,
    uint32_t a0, uint32_t a1, uint32_t a2, uint32_t a3,
    uint32_t b0, uint32_t b1)
{
    asm volatile(
        "mma.sync.aligned.m16n8k16.row.col.f32.bf16.bf16.f32 "
        "{%0,%1,%2,%3}, {%4,%5,%6,%7}, {%8,%9}, {%0,%1,%2,%3};"
        : "+f"(d0), "+f"(d1), "+f"(d2), "+f"(d3)
        : "r"(a0), "r"(a1), "r"(a2), "r"(a3), "r"(b0), "r"(b1));
}
static __device__ __forceinline__ void ldsm_x4(
    uint32_t& a0, uint32_t& a1, uint32_t& a2, uint32_t& a3, uint32_t addr)
{
    asm volatile(
        "ldmatrix.sync.aligned.m8n8.x4.shared.b16 {%0,%1,%2,%3}, [%4];"
        : "=r"(a0), "=r"(a1), "=r"(a2), "=r"(a3) : "r"(addr));
}
static __device__ __forceinline__ void cp4z(uint32_t dst, const void* src, uint32_t sz) {
    asm volatile("cp.async.ca.shared.global [%0], [%1], 4, %2;"
                 :: "r"(dst), "l"(src), "r"(sz) : "memory");
}
static __device__ __forceinline__ void cp16(uint32_t dst, const void* src) {
    asm volatile("cp.async.cg.shared.global [%0], [%1], 16;"
                 :: "r"(dst), "l"(src) : "memory");
}

// ============================================================
// prep_y: y[n][k][p] -> g_yh/g_yl [n][px][32 kp]
// ============================================================
__global__ void __launch_bounds__(256) prep_y(const float* __restrict__ y)
{
    __shared__ float s[64][65];
    const int n  = blockIdx.y;
    const int p0 = blockIdx.x * 64;
    const int tid = threadIdx.x;
#pragma unroll
    for (int pass = 0; pass < 16; pass++) {
        int fid = tid + pass * 256;
        int k = fid >> 6, px = fid & 63;
        s[k][px] = __ldg(y + ((size_t)n * 64 + k) * PP + p0 + px);
    }
    __syncthreads();
    const int px = tid >> 2, q = tid & 3;
    unsigned hb[8], lb[8];
#pragma unroll
    for (int j = 0; j < 8; j++) {
        int k = q * 16 + j * 2;
        unsigned short h0, l0, h1, l1;
        bsplit(s[k][px], h0, l0);
        bsplit(s[k + 1][px], h1, l1);
        hb[j] = pk(h0, h1);
        lb[j] = pk(l0, l1);
    }
    size_t base = ((size_t)n * PP + p0 + px) * 32 + q * 8;
    *(uint4*)(g_yh + base)     = make_uint4(hb[0], hb[1], hb[2], hb[3]);
    *(uint4*)(g_yh + base + 4) = make_uint4(hb[4], hb[5], hb[6], hb[7]);
    *(uint4*)(g_yl + base)     = make_uint4(lb[0], lb[1], lb[2], lb[3]);
    *(uint4*)(g_yl + base + 4) = make_uint4(lb[4], lb[5], lb[6], lb[7]);
}

// ============================================================
// prep_w1: gen_w[o][k] -> g_w1h/l [o][32 kp]
// ============================================================
__global__ void prep_w1(const float* __restrict__ gen_w)
{
    int idx = blockIdx.x * 256 + threadIdx.x;
    if (idx < OO * 32) {
        int o = idx >> 5, kp = idx & 31;
        unsigned short h0, l0, h1, l1;
        bsplit(__ldg(gen_w + (size_t)o * 64 + 2 * kp), h0, l0);
        bsplit(__ldg(gen_w + (size_t)o * 64 + 2 * kp + 1), h1, l1);
        g_w1h[idx] = pk(h0, h1);
        g_w1l[idx] = pk(l0, l1);
    }
}

// ============================================================
// prep_w3: fuse_w[co][ci*9+tap] -> g_wB[chunk][tap][kp][co]
// ============================================================
__global__ void prep_w3(const float* __restrict__ fuse_w)
{
    int idx = blockIdx.x * 256 + threadIdx.x;
    if (idx < 16 * 9 * 8 * 64) {
        int co  = idx & 63;
        int kp  = (idx >> 6) & 7;
        int tap = (idx >> 9) % 9;
        int chunk = idx / (64 * 8 * 9);
        int k1 = (chunk * 16 + 2 * kp) * 9 + tap;
        unsigned short h0, l0, h1, l1;
        bsplit(__ldg(fuse_w + (size_t)co * KTOT + k1), h0, l0);
        bsplit(__ldg(fuse_w + (size_t)co * KTOT + k1 + 9), h1, l1);
        g_wBh[idx] = pk(h0, h1);
        g_wBl[idx] = pk(l0, l1);
    }
}

// ============================================================
// Stage 1 (mma, 256 thr, ldmatrix, smem-staged epilogue)
// Tile 128px x 64o, K=64. Warps: wm = px half, wn = 16-o quarter.
// ============================================================
#define S1_AH 0
#define S1_AL 18432
#define S1_BH 36864
#define S1_BL 46080
#define S1_SM 55296

__global__ void __launch_bounds__(256) stage1_mma(const float* __restrict__ gen_b)
{
    extern __shared__ __align__(16) char sm[];
    const uint32_t sbase = smem_u32(sm);
    const int n  = blockIdx.z;
    const int o0 = blockIdx.y * 64;
    const int p0 = blockIdx.x * 128;
    const int tid = threadIdx.x;
    const int warp = tid >> 5, lane = tid & 31;
    const int g = lane >> 2, t = lane & 3;
    const int wm = warp & 1, wn = warp >> 1;     // wm: 64px half; wn: 16o quarter
    const int rsel = lane & 15;
    const int half16 = (lane >> 4) * 16;

    // Loaders
    {
        const uint4* yh = (const uint4*)(g_yh + ((size_t)n * PP + p0) * 32);
        const uint4* yl = (const uint4*)(g_yl + ((size_t)n * PP + p0) * 32);
#pragma unroll
        for (int pass = 0; pass < 4; pass++) {
            int fid = tid + pass * 256;          // 0..1023
            int r = fid >> 3, q = fid & 7;
            *(uint4*)(sm + S1_AH + r * 144 + q * 16) = yh[r * 8 + q];
            *(uint4*)(sm + S1_AL + r * 144 + q * 16) = yl[r * 8 + q];
        }
        const uint4* wh = (const uint4*)(g_w1h + (size_t)o0 * 32);
        const uint4* wl = (const uint4*)(g_w1l + (size_t)o0 * 32);
#pragma unroll
        for (int pass = 0; pass < 2; pass++) {
            int fid = tid + pass * 256;          // 0..511
            int r = fid >> 3, q = fid & 7;
            *(uint4*)(sm + S1_BH + r * 144 + q * 16) = wh[r * 8 + q];
            *(uint4*)(sm + S1_BL + r * 144 + q * 16) = wl[r * 8 + q];
        }
    }
    __syncthreads();

    float d[4][2][4];
#pragma unroll
    for (int i = 0; i < 4; i++)
#pragma unroll
        for (int j = 0; j < 2; j++)
#pragma unroll
            for (int r = 0; r < 4; r++) d[i][j][r] = 0.f;

#pragma unroll
    for (int s = 0; s < 3; s++) {
        const uint32_t Aoff = (s < 2) ? S1_AH : S1_AL;
        const char* B = sm + ((s == 1) ? S1_BL : S1_BH);
#pragma unroll
        for (int ks = 0; ks < 4; ks++) {
            const int kb = ks * 32;
            uint32_t a[4][4], b[2][2];
#pragma unroll
            for (int mi = 0; mi < 4; mi++)
                ldsm_x4(a[mi][0], a[mi][1], a[mi][2], a[mi][3],
                        sbase + Aoff + (wm * 64 + mi * 16 + rsel) * 144 + kb + half16);
#pragma unroll
            for (int ni = 0; ni < 2; ni++) {
                const char* p = B + (wn * 16 + ni * 8 + g) * 144 + kb + t * 4;
                b[ni][0] = *(const uint32_t*)p;
                b[ni][1] = *(const uint32_t*)(p + 16);
            }
#pragma unroll
            for (int mi = 0; mi < 4; mi++)
#pragma unroll
                for (int ni = 0; ni < 2; ni++)
                    mma16816(d[mi][ni][0], d[mi][ni][1], d[mi][ni][2], d[mi][ni][3],
                             a[mi][0], a[mi][1], a[mi][2], a[mi][3],
                             b[ni][0], b[ni][1]);
        }
    }

    // Epilogue: transpose via smem [64 o][132 px] then fully coalesced STG
    __syncthreads();
    float* smf = (float*)sm;
#pragma unroll
    for (int mi = 0; mi < 4; mi++) {
        int px = wm * 64 + mi * 16 + g;
#pragma unroll
        for (int ni = 0; ni < 2; ni++) {
            int o = wn * 16 + ni * 8 + 2 * t;
            smf[o * 132 + px]           = d[mi][ni][0];
            smf[(o + 1) * 132 + px]     = d[mi][ni][1];
            smf[o * 132 + px + 8]       = d[mi][ni][2];
            smf[(o + 1) * 132 + px + 8] = d[mi][ni][3];
        }
    }
    __syncthreads();
#pragma unroll
    for (int it = 0; it < 8; it++) {
        int f = it * 256 + tid;                 // float4 id 0..2047
        int o = f >> 5, px4 = f & 31;
        float4 v = *(float4*)&smf[o * 132 + px4 * 4];
        float bb = __ldg(gen_b + o0 + o);
        v.x += bb; v.y += bb; v.z += bb; v.w += bb;
        *(float4*)(g_kern + ((size_t)n * OO + o0 + o) * PP + p0 + px4 * 4) = v;
    }
}

// ============================================================
// Stage 2: dynamic convs for a channel PAIR + emit bf16-split cat pairs
// (unchanged from R6)
// ============================================================
__global__ void __launch_bounds__(256) stage2_dynconv(const float* __restrict__ x)
{
    const int n = blockIdx.z;
    const int cp = blockIdx.y;
    const int c0 = cp * 2;
    const int p = blockIdx.x * 256 + threadIdx.x;
    const int h = p / WW;
    const int w = p - h * WW;

    const float* xc0 = x + ((size_t)n * CC + c0) * PP;
    const float* xc1 = xc0 + PP;
    const float* kb0 = g_kern + ((size_t)n * OO + c0 * 9) * PP + p;
    const float* kb1 = kb0 + (size_t)9 * PP;

    float a0 = 0.f, a1 = 0.f, a2 = 0.f;
    float b0 = 0.f, b1 = 0.f, b2 = 0.f;
#pragma unroll
    for (int tap = 0; tap < 9; tap++) {
        const int di = tap / 3 - 1;
        const int dj = tap % 3 - 1;
        {
            int hh = h + di, ww2 = w + dj;
            bool ok = ((unsigned)hh < (unsigned)HH && (unsigned)ww2 < (unsigned)WW);
            float x0 = ok ? __ldg(xc0 + hh * WW + ww2) : 0.f;
            float x1 = ok ? __ldg(xc1 + hh * WW + ww2) : 0.f;
            a0 += x0 * __ldg(kb0 + (size_t)tap * PP);
            b0 += x1 * __ldg(kb1 + (size_t)tap * PP);
        }
        {
            int hh = h + di * 3, ww2 = w + dj * 3;
            bool ok = ((unsigned)hh < (unsigned)HH && (unsigned)ww2 < (unsigned)WW);
            float x0 = ok ? __ldg(xc0 + hh * WW + ww2) : 0.f;
            float x1 = ok ? __ldg(xc1 + hh * WW + ww2) : 0.f;
            a1 += x0 * __ldg(kb0 + (size_t)(576 + tap) * PP);
            b1 += x1 * __ldg(kb1 + (size_t)(576 + tap) * PP);
        }
        {
            int hh = h + di * 5, ww2 = w + dj * 5;
            bool ok = ((unsigned)hh < (unsigned)HH && (unsigned)ww2 < (unsigned)WW);
            float x0 = ok ? __ldg(xc0 + hh * WW + ww2) : 0.f;
            float x1 = ok ? __ldg(xc1 + hh * WW + ww2) : 0.f;
            a2 += x0 * __ldg(kb0 + (size_t)(1152 + tap) * PP);
            b2 += x1 * __ldg(kb1 + (size_t)(1152 + tap) * PP);
        }
    }

    float ev[4], ov[4];
    ev[0] = __ldg(xc0 + p); ov[0] = __ldg(xc1 + p);
    ev[1] = a0; ov[1] = b0;
    ev[2] = a1; ov[2] = b1;
    ev[3] = a2; ov[3] = b2;
#pragma unroll
    for (int sec = 0; sec < 4; sec++) {
        unsigned short he, le, ho, lo;
        bsplit(ev[sec], he, le);
        bsplit(ov[sec], ho, lo);
        size_t gi = ((size_t)n * 128 + sec * 32 + cp) * PP + p;
        g_ch[gi] = pk(he, ho);
        g_cl[gi] = pk(le, lo);
    }
}

// ============================================================
// Stage 3 (mma + ldmatrix + cp.async double-buffer)
// CTA = 1 row x 32 co, 128 thr (4 warps: 2m x 2n). grid (96, 2, 4).
// Per stage: A_h[3dy][100px][12kp] A_l ... B_h[72][40] B_l.
// ============================================================
#define S3_STG   51840
#define S3_AL_O  14400
#define S3_BH_O  28800
#define S3_BL_O  40320
#define S3_SM    (2 * S3_STG)     // 103680

__global__ void __launch_bounds__(128) stage3_mma(
    const float* __restrict__ fuse_b, float* __restrict__ out)
{
    extern __shared__ __align__(16) char sm[];
    const uint32_t sbase = smem_u32(sm);
    const int h   = blockIdx.x;
    const int coh = blockIdx.y;
    const int n   = blockIdx.z;
    const int tid = threadIdx.x;
    const int warp = tid >> 5, lane = tid & 31;
    const int g = lane >> 2, t = lane & 3;
    const int wm = warp & 1, wn = warp >> 1;     // wm: 48px half; wn: 16co half
    const int rsel = lane & 15;
    const int half16 = (lane >> 4) * 16;

    auto prefetch = [&](int chunk, uint32_t so) {
        // A: 24 (dy,kp) rows x 98 u, 4B zero-fill cp.async
        if (tid < 98) {
            const int u = tid, w = u - 1;
            const bool wok = (unsigned)w < (unsigned)WW;
#pragma unroll
            for (int r = 0; r < 24; r++) {
                int dy = r >> 3, kpl = r & 7;
                int hh = h + dy - 1;
                uint32_t sz = (wok && (unsigned)hh < (unsigned)HH) ? 4u : 0u;
                size_t gi = ((size_t)n * 128 + chunk * 8 + kpl) * PP
                            + (sz ? (hh * WW + w) : 0);
                uint32_t doff = sbase + so + (uint32_t)(((dy * 100 + u) * 12 + kpl) * 4);
                cp4z(doff,           g_ch + gi, sz);
                cp4z(doff + S3_AL_O, g_cl + gi, sz);
            }
        }
        // B: 72 tapk x 32 co, 16B cp.async
#pragma unroll
        for (int ps = 0; ps < 5; ps++) {
            int fid = tid + ps * 128;            // 0..575 used
            if (fid < 576) {
                int tapk = fid >> 3, q = fid & 7;
                size_t gi = ((size_t)chunk * 72 + tapk) * 64 + coh * 32 + q * 4;
                uint32_t doff = sbase + so + S3_BH_O + (uint32_t)((tapk * 40 + q * 4) * 4);
                cp16(doff,                       g_wBh + gi);
                cp16(doff + (S3_BL_O - S3_BH_O), g_wBl + gi);
            }
        }
        asm volatile("cp.async.commit_group;" ::: "memory");
    };

    float d[3][2][4];
#pragma unroll
    for (int i = 0; i < 3; i++)
#pragma unroll
        for (int j = 0; j < 2; j++)
#pragma unroll
            for (int q = 0; q < 4; q++) d[i][j][q] = 0.f;

    prefetch(0, 0);

#pragma unroll 1
    for (int chunk = 0; chunk < 16; chunk++) {
        const uint32_t so = (chunk & 1) ? S3_STG : 0;
        if (chunk + 1 < 16) {
            prefetch(chunk + 1, ((chunk + 1) & 1) ? S3_STG : 0);
            asm volatile("cp.async.wait_group 1;" ::: "memory");
        } else {
            asm volatile("cp.async.wait_group 0;" ::: "memory");
        }
        __syncthreads();

#pragma unroll
        for (int s = 0; s < 3; s++) {
            const uint32_t Ab = sbase + so + ((s < 2) ? 0u : (uint32_t)S3_AL_O)
                                + rsel * 48 + half16;
            const char* Bp = sm + so + ((s == 1) ? S3_BL_O : S3_BH_O);
#pragma unroll
            for (int tap = 0; tap < 9; tap++) {
                const int dy = tap / 3, dx = tap % 3;
                uint32_t b[2][2];
#pragma unroll
                for (int ni = 0; ni < 2; ni++) {
                    int coL = wn * 16 + ni * 8 + g;
                    b[ni][0] = *(const uint32_t*)(Bp + ((tap * 8 + t) * 40 + coL) * 4);
                    b[ni][1] = *(const uint32_t*)(Bp + ((tap * 8 + t + 4) * 40 + coL) * 4);
                }
#pragma unroll
                for (int mi = 0; mi < 3; mi++) {
                    int px0 = wm * 48 + mi * 16 + dx;
                    uint32_t a0, a1, a2, a3;
                    ldsm_x4(a0, a1, a2, a3, Ab + (dy * 100 + px0) * 48);
#pragma unroll
                    for (int ni = 0; ni < 2; ni++)
                        mma16816(d[mi][ni][0], d[mi][ni][1], d[mi][ni][2], d[mi][ni][3],
                                 a0, a1, a2, a3, b[ni][0], b[ni][1]);
                }
            }
        }
        __syncthreads();
    }

    // Epilogue
#pragma unroll
    for (int mi = 0; mi < 3; mi++) {
        int pxcol = wm * 48 + mi * 16 + g;
#pragma unroll
        for (int ni = 0; ni < 2; ni++) {
            int co = coh * 32 + wn * 16 + ni * 8 + 2 * t;
            float b0v = __ldg(fuse_b + co);
            float b1v = __ldg(fuse_b + co + 1);
            float* r0 = out + ((size_t)n * CC + co) * PP + h * WW;
            float* r1 = r0 + PP;
            r0[pxcol]     = d[mi][ni][0] + b0v;
            r1[pxcol]     = d[mi][ni][1] + b1v;
            r0[pxcol + 8] = d[mi][ni][2] + b0v;
            r1[pxcol + 8] = d[mi][ni][3] + b1v;
        }
    }
}

// ============================================================
extern "C" void kernel_launch(void* const* d_in, const int* in_sizes, int n_in,
                              void* d_out, int out_size)
{
    (void)in_sizes; (void)n_in; (void)out_size;
    const float* x      = (const float*)d_in[0];
    const float* y      = (const float*)d_in[1];
    const float* gen_w  = (const float*)d_in[2];
    const float* gen_b  = (const float*)d_in[3];
    const float* fuse_w = (const float*)d_in[4];
    const float* fuse_b = (const float*)d_in[5];
    float* out = (float*)d_out;

    cudaFuncSetAttribute(stage1_mma, cudaFuncAttributeMaxDynamicSharedMemorySize, S1_SM);
    cudaFuncSetAttribute(stage3_mma, cudaFuncAttributeMaxDynamicSharedMemorySize, S3_SM);

    prep_y<<<dim3(PP / 64, NN), 256>>>(y);
    prep_w1<<<(OO * 32 + 255) / 256, 256>>>(gen_w);
    prep_w3<<<(16 * 9 * 8 * 64 + 255) / 256, 256>>>(fuse_w);

    stage1_mma<<<dim3(PP / 128, OO / 64, NN), 256, S1_SM>>>(gen_b);

    stage2_dynconv<<<dim3(PP / 256, CC / 2, NN), 256>>>(x);

    stage3_mma<<<dim3(HH, 2, NN), 128, S3_SM>>>(fuse_b, out);
}

// round 8
// speedup vs baseline: 2.5896x; 1.3180x over previous
#include <cuda_runtime.h>
#include <cuda_bf16.h>
#include <cstdint>

// Problem constants
#define NN 4
#define CC 64
#define HH 96
#define WW 96
#define PP (HH * WW)       // 9216
#define OO 1728            // 3*C*9
#define KTOT 2304          // 256*9

// Scratch (__device__ globals per alloc-free rule)
__device__ unsigned g_ch[(size_t)NN * 128 * PP];    // cat bf16-hi pairs [n][ci_pair][px]
__device__ unsigned g_cl[(size_t)NN * 128 * PP];    // cat bf16-lo pairs
__device__ unsigned g_yh[(size_t)NN * PP * 32];     // y transposed bf16-hi pairs [n][px][kp]
__device__ unsigned g_yl[(size_t)NN * PP * 32];
__device__ unsigned g_w1h[OO * 32];                 // gen_w bf16 pairs, REORDERED o' = dil*576+tap*64+c
__device__ unsigned g_w1l[OO * 32];
__device__ float    g_b1[OO];                       // gen_b reordered to o'
__device__ unsigned g_wBh[16 * 9 * 8 * 64];         // fuse_w packed [chunk][tap][kp][co]
__device__ unsigned g_wBl[16 * 9 * 8 * 64];

// ---- bf16 split helpers ----
static __device__ __forceinline__ void bsplit(float v, unsigned short& h, unsigned short& l) {
    __nv_bfloat16 bh = __float2bfloat16_rn(v);
    float r = v - __bfloat162float(bh);
    __nv_bfloat16 bl = __float2bfloat16_rn(r);
    h = __bfloat16_as_ushort(bh);
    l = __bfloat16_as_ushort(bl);
}
static __device__ __forceinline__ unsigned pk(unsigned short lo, unsigned short hi) {
    return ((unsigned)hi << 16) | lo;
}
static __device__ __forceinline__ uint32_t smem_u32(const void* p) {
    uint32_t a;
    asm("{ .reg .u64 t; cvta.to.shared.u64 t, %1; cvt.u32.u64 %0, t; }" : "=r"(a) : "l"(p));
    return a;
}

// ---- warp mma m16n8k16 bf16 + ldmatrix + cp.async ----
static __device__ __forceinline__ void mma16816(
    float& d0, float& d1, float& d2, float& d3,
    uint32_t a0, uint32_t a1, uint32_t a2, uint32_t a3,
    uint32_t b0, uint32_t b1)
{
    asm volatile(
        "mma.sync.aligned.m16n8k16.row.col.f32.bf16.bf16.f32 "
        "{%0,%1,%2,%3}, {%4,%5,%6,%7}, {%8,%9}, {%0,%1,%2,%3};"
        : "+f"(d0), "+f"(d1), "+f"(d2), "+f"(d3)
        : "r"(a0), "r"(a1), "r"(a2), "r"(a3), "r"(b0), "r"(b1));
}
static __device__ __forceinline__ void ldsm_x4(
    uint32_t& a0, uint32_t& a1, uint32_t& a2, uint32_t& a3, uint32_t addr)
{
    asm volatile(
        "ldmatrix.sync.aligned.m8n8.x4.shared.b16 {%0,%1,%2,%3}, [%4];"
        : "=r"(a0), "=r"(a1), "=r"(a2), "=r"(a3) : "r"(addr));
}
static __device__ __forceinline__ void cp4z(uint32_t dst, const void* src, uint32_t sz) {
    asm volatile("cp.async.ca.shared.global [%0], [%1], 4, %2;"
                 :: "r"(dst), "l"(src), "r"(sz) : "memory");
}
static __device__ __forceinline__ void cp16(uint32_t dst, const void* src) {
    asm volatile("cp.async.cg.shared.global [%0], [%1], 16;"
                 :: "r"(dst), "l"(src) : "memory");
}

// ============================================================
// prep_y: y[n][k][p] -> g_yh/g_yl [n][px][32 kp]
// ============================================================
__global__ void __launch_bounds__(256) prep_y(const float* __restrict__ y)
{
    __shared__ float s[64][65];
    const int n  = blockIdx.y;
    const int p0 = blockIdx.x * 64;
    const int tid = threadIdx.x;
#pragma unroll
    for (int pass = 0; pass < 16; pass++) {
        int fid = tid + pass * 256;
        int k = fid >> 6, px = fid & 63;
        s[k][px] = __ldg(y + ((size_t)n * 64 + k) * PP + p0 + px);
    }
    __syncthreads();
    const int px = tid >> 2, q = tid & 3;
    unsigned hb[8], lb[8];
#pragma unroll
    for (int j = 0; j < 8; j++) {
        int k = q * 16 + j * 2;
        unsigned short h0, l0, h1, l1;
        bsplit(s[k][px], h0, l0);
        bsplit(s[k + 1][px], h1, l1);
        hb[j] = pk(h0, h1);
        lb[j] = pk(l0, l1);
    }
    size_t base = ((size_t)n * PP + p0 + px) * 32 + q * 8;
    *(uint4*)(g_yh + base)     = make_uint4(hb[0], hb[1], hb[2], hb[3]);
    *(uint4*)(g_yh + base + 4) = make_uint4(hb[4], hb[5], hb[6], hb[7]);
    *(uint4*)(g_yl + base)     = make_uint4(lb[0], lb[1], lb[2], lb[3]);
    *(uint4*)(g_yl + base + 4) = make_uint4(lb[4], lb[5], lb[6], lb[7]);
}

// ============================================================
// prep_w1: gen_w -> g_w1h/l with row reorder o' = dil*576 + tap*64 + c
// (src row = dil*576 + c*9 + tap). Also reorders gen_b into g_b1.
// ============================================================
__global__ void prep_w1(const float* __restrict__ gen_w, const float* __restrict__ gen_b)
{
    int idx = blockIdx.x * 256 + threadIdx.x;
    if (idx < OO * 32) {
        int op = idx >> 5, kp = idx & 31;
        int dil = op / 576;
        int rem = op - dil * 576;
        int tap = rem >> 6;
        int c   = rem & 63;
        int src = dil * 576 + c * 9 + tap;
        unsigned short h0, l0, h1, l1;
        bsplit(__ldg(gen_w + (size_t)src * 64 + 2 * kp), h0, l0);
        bsplit(__ldg(gen_w + (size_t)src * 64 + 2 * kp + 1), h1, l1);
        g_w1h[idx] = pk(h0, h1);
        g_w1l[idx] = pk(l0, l1);
        if (kp == 0) g_b1[op] = __ldg(gen_b + src);
    }
}

// ============================================================
// prep_w3: fuse_w[co][ci*9+tap] -> g_wB[chunk][tap][kp][co]
// ============================================================
__global__ void prep_w3(const float* __restrict__ fuse_w)
{
    int idx = blockIdx.x * 256 + threadIdx.x;
    if (idx < 16 * 9 * 8 * 64) {
        int co  = idx & 63;
        int kp  = (idx >> 6) & 7;
        int tap = (idx >> 9) % 9;
        int chunk = idx / (64 * 8 * 9);
        int k1 = (chunk * 16 + 2 * kp) * 9 + tap;
        unsigned short h0, l0, h1, l1;
        bsplit(__ldg(fuse_w + (size_t)co * KTOT + k1), h0, l0);
        bsplit(__ldg(fuse_w + (size_t)co * KTOT + k1 + 9), h1, l1);
        g_wBh[idx] = pk(h0, h1);
        g_wBl[idx] = pk(l0, l1);
    }
}

// ============================================================
// FUSED stage1+2: per CTA = 128 px, all 64 channels, 27 (dil,tap) chunks.
// kern tile [128px x 64c] computed by mma for chunk (dil,tap), consumed
// immediately: acc[c][px] += (kern + bias) * x[c, p+shift]; acc -> cat pairs.
// Also writes the x-passthrough cat section. grid (72, NN), 256 thr.
// ============================================================
#define F_AH 0
#define F_AL 18432
#define F_B0 36864                  // buffer 0: BH then BL
#define F_BSTG 18432                // 2 * 64*144
#define F_SM (36864 + 2 * 18432)    // 73728

__global__ void __launch_bounds__(256) fused12(const float* __restrict__ x)
{
    extern __shared__ __align__(16) char sm[];
    const uint32_t sbase = smem_u32(sm);
    const int n  = blockIdx.y;
    const int p0 = blockIdx.x * 128;
    const int tid = threadIdx.x;
    const int warp = tid >> 5, lane = tid & 31;
    const int g = lane >> 2, t = lane & 3;
    const int wm = warp & 1, wn = warp >> 1;   // wm: 64px half; wn: 16c quarter
    const int rsel = lane & 15;
    const int half16 = (lane >> 4) * 16;

    // ---- load persistent A (y) tile ----
    {
        const uint4* yh = (const uint4*)(g_yh + ((size_t)n * PP + p0) * 32);
        const uint4* yl = (const uint4*)(g_yl + ((size_t)n * PP + p0) * 32);
#pragma unroll
        for (int pass = 0; pass < 4; pass++) {
            int fid = tid + pass * 256;          // 0..1023 float4 ids
            int r = fid >> 3, q = fid & 7;
            *(uint4*)(sm + F_AH + r * 144 + q * 16) = yh[r * 8 + q];
            *(uint4*)(sm + F_AL + r * 144 + q * 16) = yl[r * 8 + q];
        }
    }

    // ---- per-element pixel coords (px_e for mi 0..3, r 0..1) ----
    int hE[8], wE[8];
#pragma unroll
    for (int mi = 0; mi < 4; mi++)
#pragma unroll
        for (int r = 0; r < 2; r++) {
            int px = wm * 64 + mi * 16 + g + 8 * r;
            int p  = p0 + px;
            hE[mi * 2 + r] = p / WW;
            wE[mi * 2 + r] = p - (p / WW) * WW;
        }

    // ---- x passthrough section (sec 0) ----
#pragma unroll
    for (int mi = 0; mi < 4; mi++)
#pragma unroll
        for (int r = 0; r < 2; r++) {
            int px = wm * 64 + mi * 16 + g + 8 * r;
#pragma unroll
            for (int ni = 0; ni < 2; ni++) {
                int ce = wn * 16 + ni * 8 + 2 * t;
                float v0 = __ldg(x + ((size_t)n * CC + ce) * PP + p0 + px);
                float v1 = __ldg(x + ((size_t)n * CC + ce + 1) * PP + p0 + px);
                unsigned short he, le, ho, lo;
                bsplit(v0, he, le);
                bsplit(v1, ho, lo);
                int cpair = wn * 8 + ni * 4 + t;
                size_t gi = ((size_t)n * 128 + cpair) * PP + p0 + px;
                g_ch[gi] = pk(he, ho);
                g_cl[gi] = pk(le, lo);
            }
        }

    // ---- B prefetch helper ----
    auto prefetch = [&](int ch, uint32_t so) {
#pragma unroll
        for (int ps = 0; ps < 2; ps++) {
            int fid = tid + ps * 256;            // 0..511
            int o = fid >> 3, q = fid & 7;
            size_t gi = ((size_t)(ch * 64 + o)) * 32 + q * 4;
            uint32_t doff = sbase + so + (uint32_t)(o * 144 + q * 16);
            cp16(doff,          g_w1h + gi);
            cp16(doff + 9216,   g_w1l + gi);
        }
        asm volatile("cp.async.commit_group;" ::: "memory");
    };

    prefetch(0, F_B0);
    __syncthreads();   // covers A stores too

    const float* xn = x + (size_t)n * CC * PP;

#pragma unroll 1
    for (int dil = 0; dil < 3; dil++) {
        float acc[4][2][4];
#pragma unroll
        for (int i = 0; i < 4; i++)
#pragma unroll
            for (int j = 0; j < 2; j++)
#pragma unroll
                for (int q = 0; q < 4; q++) acc[i][j][q] = 0.f;

        const int dd = 2 * dil + 1;

#pragma unroll 1
        for (int tap = 0; tap < 9; tap++) {
            const int ch = dil * 9 + tap;
            const uint32_t so = (ch & 1) ? (F_B0 + F_BSTG) : F_B0;
            if (ch + 1 < 27) {
                prefetch(ch + 1, ((ch + 1) & 1) ? (F_B0 + F_BSTG) : F_B0);
                asm volatile("cp.async.wait_group 1;" ::: "memory");
            } else {
                asm volatile("cp.async.wait_group 0;" ::: "memory");
            }
            __syncthreads();

            // ---- MMA: kern tile for (dil,tap), all 64 c ----
            float d[4][2][4];
#pragma unroll
            for (int i = 0; i < 4; i++)
#pragma unroll
                for (int j = 0; j < 2; j++)
#pragma unroll
                    for (int q = 0; q < 4; q++) d[i][j][q] = 0.f;

            const char* BH = sm + so;
            const char* BL = sm + so + 9216;
#pragma unroll
            for (int ks = 0; ks < 4; ks++) {
                const int kb = ks * 32;
                uint32_t aH[4][4], aL[4][4], bH[2][2], bL[2][2];
#pragma unroll
                for (int mi = 0; mi < 4; mi++) {
                    ldsm_x4(aH[mi][0], aH[mi][1], aH[mi][2], aH[mi][3],
                            sbase + F_AH + (wm * 64 + mi * 16 + rsel) * 144 + kb + half16);
                    ldsm_x4(aL[mi][0], aL[mi][1], aL[mi][2], aL[mi][3],
                            sbase + F_AL + (wm * 64 + mi * 16 + rsel) * 144 + kb + half16);
                }
#pragma unroll
                for (int ni = 0; ni < 2; ni++) {
                    const char* pH = BH + (wn * 16 + ni * 8 + g) * 144 + kb + t * 4;
                    const char* pL = BL + (wn * 16 + ni * 8 + g) * 144 + kb + t * 4;
                    bH[ni][0] = *(const uint32_t*)pH;
                    bH[ni][1] = *(const uint32_t*)(pH + 16);
                    bL[ni][0] = *(const uint32_t*)pL;
                    bL[ni][1] = *(const uint32_t*)(pL + 16);
                }
#pragma unroll
                for (int mi = 0; mi < 4; mi++)
#pragma unroll
                    for (int ni = 0; ni < 2; ni++) {
                        mma16816(d[mi][ni][0], d[mi][ni][1], d[mi][ni][2], d[mi][ni][3],
                                 aH[mi][0], aH[mi][1], aH[mi][2], aH[mi][3],
                                 bH[ni][0], bH[ni][1]);
                        mma16816(d[mi][ni][0], d[mi][ni][1], d[mi][ni][2], d[mi][ni][3],
                                 aH[mi][0], aH[mi][1], aH[mi][2], aH[mi][3],
                                 bL[ni][0], bL[ni][1]);
                        mma16816(d[mi][ni][0], d[mi][ni][1], d[mi][ni][2], d[mi][ni][3],
                                 aL[mi][0], aL[mi][1], aL[mi][2], aL[mi][3],
                                 bH[ni][0], bH[ni][1]);
                    }
            }
            __syncthreads();   // B buffer free for next prefetch

            // ---- consume: acc += (kern + bias) * x_shifted ----
            const int did = (tap / 3 - 1) * dd;
            const int djd = (tap % 3 - 1) * dd;
            const int soff = did * WW + djd;
            float2 bias[2];
#pragma unroll
            for (int ni = 0; ni < 2; ni++)
                bias[ni] = __ldg((const float2*)(g_b1 + ch * 64 + wn * 16 + ni * 8 + 2 * t));

#pragma unroll
            for (int mi = 0; mi < 4; mi++)
#pragma unroll
                for (int r = 0; r < 2; r++) {
                    const int e = mi * 2 + r;
                    const bool vok = ((unsigned)(hE[e] + did) < (unsigned)HH) &&
                                     ((unsigned)(wE[e] + djd) < (unsigned)WW);
                    const int px = wm * 64 + mi * 16 + g + 8 * r;
                    const int pa = p0 + px + soff;
#pragma unroll
                    for (int ni = 0; ni < 2; ni++) {
                        const int ce = wn * 16 + ni * 8 + 2 * t;
                        float x0 = 0.f, x1 = 0.f;
                        if (vok) {
                            x0 = __ldg(xn + (size_t)ce * PP + pa);
                            x1 = __ldg(xn + (size_t)(ce + 1) * PP + pa);
                        }
                        acc[mi][ni][r * 2 + 0] += (d[mi][ni][r * 2 + 0] + bias[ni].x) * x0;
                        acc[mi][ni][r * 2 + 1] += (d[mi][ni][r * 2 + 1] + bias[ni].y) * x1;
                    }
                }
        }

        // ---- write cat section (dil+1) as bf16 pairs ----
#pragma unroll
        for (int mi = 0; mi < 4; mi++)
#pragma unroll
            for (int r = 0; r < 2; r++) {
                int px = wm * 64 + mi * 16 + g + 8 * r;
#pragma unroll
                for (int ni = 0; ni < 2; ni++) {
                    unsigned short he, le, ho, lo;
                    bsplit(acc[mi][ni][r * 2 + 0], he, le);
                    bsplit(acc[mi][ni][r * 2 + 1], ho, lo);
                    int cpair = wn * 8 + ni * 4 + t;
                    size_t gi = ((size_t)n * 128 + (dil + 1) * 32 + cpair) * PP + p0 + px;
                    g_ch[gi] = pk(he, ho);
                    g_cl[gi] = pk(le, lo);
                }
            }
    }
}

// ============================================================
// Stage 3 (unchanged from R7): mma + ldmatrix + cp.async double-buffer
// ============================================================
#define S3_STG   51840
#define S3_AL_O  14400
#define S3_BH_O  28800
#define S3_BL_O  40320
#define S3_SM    (2 * S3_STG)

__global__ void __launch_bounds__(128) stage3_mma(
    const float* __restrict__ fuse_b, float* __restrict__ out)
{
    extern __shared__ __align__(16) char sm[];
    const uint32_t sbase = smem_u32(sm);
    const int h   = blockIdx.x;
    const int coh = blockIdx.y;
    const int n   = blockIdx.z;
    const int tid = threadIdx.x;
    const int warp = tid >> 5, lane = tid & 31;
    const int g = lane >> 2, t = lane & 3;
    const int wm = warp & 1, wn = warp >> 1;
    const int rsel = lane & 15;
    const int half16 = (lane >> 4) * 16;

    auto prefetch = [&](int chunk, uint32_t so) {
        if (tid < 98) {
            const int u = tid, w = u - 1;
            const bool wok = (unsigned)w < (unsigned)WW;
#pragma unroll
            for (int r = 0; r < 24; r++) {
                int dy = r >> 3, kpl = r & 7;
                int hh = h + dy - 1;
                uint32_t sz = (wok && (unsigned)hh < (unsigned)HH) ? 4u : 0u;
                size_t gi = ((size_t)n * 128 + chunk * 8 + kpl) * PP
                            + (sz ? (hh * WW + w) : 0);
                uint32_t doff = sbase + so + (uint32_t)(((dy * 100 + u) * 12 + kpl) * 4);
                cp4z(doff,           g_ch + gi, sz);
                cp4z(doff + S3_AL_O, g_cl + gi, sz);
            }
        }
#pragma unroll
        for (int ps = 0; ps < 5; ps++) {
            int fid = tid + ps * 128;
            if (fid < 576) {
                int tapk = fid >> 3, q = fid & 7;
                size_t gi = ((size_t)chunk * 72 + tapk) * 64 + coh * 32 + q * 4;
                uint32_t doff = sbase + so + S3_BH_O + (uint32_t)((tapk * 40 + q * 4) * 4);
                cp16(doff,                       g_wBh + gi);
                cp16(doff + (S3_BL_O - S3_BH_O), g_wBl + gi);
            }
        }
        asm volatile("cp.async.commit_group;" ::: "memory");
    };

    float d[3][2][4];
#pragma unroll
    for (int i = 0; i < 3; i++)
#pragma unroll
        for (int j = 0; j < 2; j++)
#pragma unroll
            for (int q = 0; q < 4; q++) d[i][j][q] = 0.f;

    prefetch(0, 0);

#pragma unroll 1
    for (int chunk = 0; chunk < 16; chunk++) {
        const uint32_t so = (chunk & 1) ? S3_STG : 0;
        if (chunk + 1 < 16) {
            prefetch(chunk + 1, ((chunk + 1) & 1) ? S3_STG : 0);
            asm volatile("cp.async.wait_group 1;" ::: "memory");
        } else {
            asm volatile("cp.async.wait_group 0;" ::: "memory");
        }
        __syncthreads();

#pragma unroll
        for (int s = 0; s < 3; s++) {
            const uint32_t Ab = sbase + so + ((s < 2) ? 0u : (uint32_t)S3_AL_O)
                                + rsel * 48 + half16;
            const char* Bp = sm + so + ((s == 1) ? S3_BL_O : S3_BH_O);
#pragma unroll
            for (int tap = 0; tap < 9; tap++) {
                const int dy = tap / 3, dx = tap % 3;
                uint32_t b[2][2];
#pragma unroll
                for (int ni = 0; ni < 2; ni++) {
                    int coL = wn * 16 + ni * 8 + g;
                    b[ni][0] = *(const uint32_t*)(Bp + ((tap * 8 + t) * 40 + coL) * 4);
                    b[ni][1] = *(const uint32_t*)(Bp + ((tap * 8 + t + 4) * 40 + coL) * 4);
                }
#pragma unroll
                for (int mi = 0; mi < 3; mi++) {
                    int px0 = wm * 48 + mi * 16 + dx;
                    uint32_t a0, a1, a2, a3;
                    ldsm_x4(a0, a1, a2, a3, Ab + (dy * 100 + px0) * 48);
#pragma unroll
                    for (int ni = 0; ni < 2; ni++)
                        mma16816(d[mi][ni][0], d[mi][ni][1], d[mi][ni][2], d[mi][ni][3],
                                 a0, a1, a2, a3, b[ni][0], b[ni][1]);
                }
            }
        }
        __syncthreads();
    }

#pragma unroll
    for (int mi = 0; mi < 3; mi++) {
        int pxcol = wm * 48 + mi * 16 + g;
#pragma unroll
        for (int ni = 0; ni < 2; ni++) {
            int co = coh * 32 + wn * 16 + ni * 8 + 2 * t;
            float b0v = __ldg(fuse_b + co);
            float b1v = __ldg(fuse_b + co + 1);
            float* r0 = out + ((size_t)n * CC + co) * PP + h * WW;
            float* r1 = r0 + PP;
            r0[pxcol]     = d[mi][ni][0] + b0v;
            r1[pxcol]     = d[mi][ni][1] + b1v;
            r0[pxcol + 8] = d[mi][ni][2] + b0v;
            r1[pxcol + 8] = d[mi][ni][3] + b1v;
        }
    }
}

// ============================================================
extern "C" void kernel_launch(void* const* d_in, const int* in_sizes, int n_in,
                              void* d_out, int out_size)
{
    (void)in_sizes; (void)n_in; (void)out_size;
    const float* x      = (const float*)d_in[0];
    const float* y      = (const float*)d_in[1];
    const float* gen_w  = (const float*)d_in[2];
    const float* gen_b  = (const float*)d_in[3];
    const float* fuse_w = (const float*)d_in[4];
    const float* fuse_b = (const float*)d_in[5];
    float* out = (float*)d_out;

    cudaFuncSetAttribute(fused12, cudaFuncAttributeMaxDynamicSharedMemorySize, F_SM);
    cudaFuncSetAttribute(stage3_mma, cudaFuncAttributeMaxDynamicSharedMemorySize, S3_SM);

    prep_y<<<dim3(PP / 64, NN), 256>>>(y);
    prep_w1<<<(OO * 32 + 255) / 256, 256>>>(gen_w, gen_b);
    prep_w3<<<(16 * 9 * 8 * 64 + 255) / 256, 256>>>(fuse_w);

    fused12<<<dim3(PP / 128, NN), 256, F_SM>>>(x);

    stage3_mma<<<dim3(HH, 2, NN), 128, S3_SM>>>(fuse_b, out);
}